// round 7
// baseline (speedup 1.0000x reference)
#include <cuda_runtime.h>
#include <cstdint>

// Problem constants
#define NPTS   131072
#define DIMK   64      // slice width (we use inpt[:, 64:128])
#define KCENT  1024
#define INROW  128     // inpt row stride

// Tiling
#define BM 64
#define BN 128
#define TM 8
#define TN 4
#define THREADS 256

#define XS_FLOATS   (BM * DIMK)                 // 4096
#define CS_FLOATS   ((DIMK / 4) * BN * 4)       // 8192 per buffer
#define SMEM_BYTES  ((XS_FLOATS + 2 * CS_FLOATS) * 4)   // 81920

__device__ float g_cnorm[KCENT];

// ---- f32x2 helpers (exact fp32 semantics, 2 FMAs per instruction) ----
__device__ __forceinline__ void fma2(unsigned long long& d,
                                     unsigned long long a,
                                     unsigned long long b) {
    asm("fma.rn.f32x2 %0, %1, %2, %0;" : "+l"(d) : "l"(a), "l"(b));
}
__device__ __forceinline__ float2 unpack2(unsigned long long v) {
    float2 f;
    asm("mov.b64 {%0, %1}, %2;" : "=f"(f.x), "=f"(f.y) : "l"(v));
    return f;
}
// 16-byte shared load producing two f32x2 operand registers
__device__ __forceinline__ void lds128(unsigned addr,
                                       unsigned long long& lo,
                                       unsigned long long& hi) {
    asm volatile(
        "{\n\t"
        ".reg .b32 t0, t1, t2, t3;\n\t"
        "ld.shared.v4.b32 {t0, t1, t2, t3}, [%2];\n\t"
        "mov.b64 %0, {t0, t1};\n\t"
        "mov.b64 %1, {t2, t3};\n\t"
        "}"
        : "=l"(lo), "=l"(hi) : "r"(addr));
}
__device__ __forceinline__ void cp_async16(unsigned smem_addr, const void* gptr) {
    asm volatile("cp.async.cg.shared.global [%0], [%1], 16;"
                 :: "r"(smem_addr), "l"(gptr));
}
__device__ __forceinline__ void cp_commit() {
    asm volatile("cp.async.commit_group;");
}
__device__ __forceinline__ void cp_wait_all() {
    asm volatile("cp.async.wait_group 0;" ::: "memory");
}

// ---- center squared norms ----
__global__ void cnorm_kernel(const float* __restrict__ centers) {
    int n = blockIdx.x * blockDim.x + threadIdx.x;
    if (n < KCENT) {
        const float* c = centers + (size_t)n * DIMK;
        float s = 0.f;
        #pragma unroll
        for (int k = 0; k < DIMK; k++) s = fmaf(c[k], c[k], s);
        g_cnorm[n] = s;
    }
}

// ---- fused GEMM + argmin, cp.async double-buffered C tiles ----
// Xs: [m][k]            64 x 64 floats (16 KB); a-reads LDS.128 broadcast
// Cs: quad-interleaved  [k/4][n][4], two 32 KB buffers;
//     b-reads LDS.128, contiguous 512B/warp (4-phase, conflict-free)
// Inner loop: per kq load 4 b-pairs, then stream a row-by-row with a 1-deep
// register prefetch; FMA order lo(j=0..3) then hi(j=0..3) keeps same-acc
// reuse distance >= 4 instructions (no fixed-lat RAW stalls).
__global__ __launch_bounds__(THREADS, 2)
void label_kernel(const float* __restrict__ inpt,
                  const float* __restrict__ centers,
                  float* __restrict__ out) {
    extern __shared__ __align__(16) float smem[];
    float* Xs = smem;                       // XS_FLOATS
    float* Cs0 = smem + XS_FLOATS;          // CS_FLOATS
    float* Cs1 = Cs0 + CS_FLOATS;           // CS_FLOATS

    const int tid = threadIdx.x;
    const int ty  = tid >> 5;
    const int tx  = tid & 31;
    const int m0  = blockIdx.x * BM;
    const int mbase = ty * TM;

    // cp.async C-tile prefetch: thread -> (n = tid/2, h = tid&1), 8 x 16B
    const int cn_row = tid >> 1;
    const int cn_h   = tid & 1;
    const float* csrc_base = centers + (size_t)cn_row * DIMK + cn_h * 32;

    // Prefetch tile 0 into Cs0 (overlaps the X-tile global loads below)
    {
        unsigned cs = (unsigned)__cvta_generic_to_shared(Cs0);
        #pragma unroll
        for (int i4 = 0; i4 < 8; i4++) {
            const int k = cn_h * 32 + i4 * 4;
            cp_async16(cs + (unsigned)(((k >> 2) * (BN * 4) + cn_row * 4) * 4),
                       csrc_base + i4 * 4);
        }
        cp_commit();
    }

    // Load X tile: rows m0..m0+63, cols 64..127 (second slice)
    {
        const int r  = tid >> 4;
        const int kg = tid & 15;
        #pragma unroll
        for (int rep = 0; rep < 4; rep++) {
            const int m = r + rep * 16;
            float4 v = *reinterpret_cast<const float4*>(
                inpt + (size_t)(m0 + m) * INROW + DIMK + kg * 4);
            *reinterpret_cast<float4*>(&Xs[m * DIMK + kg * 4]) = v;
        }
    }

    const unsigned xs_row = (unsigned)__cvta_generic_to_shared(Xs)
                          + (unsigned)(mbase * DIMK * 4);
    const unsigned cs_base0 = (unsigned)__cvta_generic_to_shared(Cs0);
    const unsigned cs_base1 = (unsigned)__cvta_generic_to_shared(Cs1);

    float bestd[TM];
    int   bestn[TM];
    #pragma unroll
    for (int i = 0; i < TM; i++) {
        bestd[i] = __int_as_float(0x7f800000);
        bestn[i] = 0;
    }

    #pragma unroll 1
    for (int t = 0; t < KCENT / BN; t++) {
        const int n0 = t * BN;
        cp_wait_all();          // C tile t landed
        __syncthreads();        // ...visible to all warps; compute(t-1) done

        // Prefetch tile t+1 into the other buffer (overlaps compute of t)
        if (t + 1 < KCENT / BN) {
            unsigned cs_next = (t & 1) ? cs_base0 : cs_base1;
            const float* src = csrc_base + (size_t)(n0 + BN) * DIMK;
            #pragma unroll
            for (int i4 = 0; i4 < 8; i4++) {
                const int k = cn_h * 32 + i4 * 4;
                cp_async16(cs_next +
                           (unsigned)(((k >> 2) * (BN * 4) + cn_row * 4) * 4),
                           src + i4 * 4);
            }
            cp_commit();
        }

        const unsigned cs_cur = ((t & 1) ? cs_base1 : cs_base0)
                              + (unsigned)(tx * 16);

        // acc[i][j] packs (sum over even k, sum over odd k)
        unsigned long long acc[TM][TN];
        #pragma unroll
        for (int i = 0; i < TM; i++)
            #pragma unroll
            for (int j = 0; j < TN; j++) acc[i][j] = 0ull;

        #pragma unroll 2
        for (int kq = 0; kq < DIMK / 4; kq++) {   // 4 k-values per step
            unsigned long long b_lo[TN], b_hi[TN];
            #pragma unroll
            for (int j = 0; j < TN; j++)
                lds128(cs_cur + (unsigned)((kq * (BN * 4) + 32 * j * 4) * 4),
                       b_lo[j], b_hi[j]);

            // Stream a rows with 1-deep register prefetch
            unsigned long long a_lo, a_hi, na_lo, na_hi;
            lds128(xs_row + (unsigned)(kq * 16), a_lo, a_hi);
            #pragma unroll
            for (int i = 0; i < TM; i++) {
                if (i + 1 < TM)
                    lds128(xs_row + (unsigned)((i + 1) * DIMK * 4 + kq * 16),
                           na_lo, na_hi);
                // lo sweep then hi sweep: same-acc reuse distance = 4 instrs
                #pragma unroll
                for (int j = 0; j < TN; j++) fma2(acc[i][j], a_lo, b_lo[j]);
                #pragma unroll
                for (int j = 0; j < TN; j++) fma2(acc[i][j], a_hi, b_hi[j]);
                a_lo = na_lo; a_hi = na_hi;
            }
        }

        // Epilogue: d = ||c||^2 - 2*dot, running argmin (ascending n ->
        // first-minimum semantics of jnp.argmin)
        float cn[TN];
        #pragma unroll
        for (int j = 0; j < TN; j++)
            cn[j] = __ldg(&g_cnorm[n0 + tx + 32 * j]);

        #pragma unroll
        for (int i = 0; i < TM; i++) {
            #pragma unroll
            for (int j = 0; j < TN; j++) {
                float2 s = unpack2(acc[i][j]);
                float d = fmaf(-2.0f, s.x, cn[j]);
                d = fmaf(-2.0f, s.y, d);
                int n = n0 + tx + 32 * j;
                if (d < bestd[i]) { bestd[i] = d; bestn[i] = n; }
            }
        }
    }

    // Warp reduction per row (lanes hold disjoint n-sets); tie -> lower index
    #pragma unroll
    for (int i = 0; i < TM; i++) {
        float d = bestd[i];
        int   n = bestn[i];
        #pragma unroll
        for (int off = 16; off > 0; off >>= 1) {
            float od = __shfl_down_sync(0xffffffffu, d, off);
            int   on = __shfl_down_sync(0xffffffffu, n, off);
            if (od < d || (od == d && on < n)) { d = od; n = on; }
        }
        // Output dtype is float32: labels 0..1023 exactly representable.
        if (tx == 0) out[m0 + mbase + i] = (float)n;
    }
}

extern "C" void kernel_launch(void* const* d_in, const int* in_sizes, int n_in,
                              void* d_out, int out_size) {
    // Identify inputs by element count (robust to metadata ordering):
    //   inpt: 16777216 elements (unique); centers1: second 65536-elem tensor
    const float* inpt     = nullptr;
    const float* centers1 = nullptr;
    int centers_seen = 0;
    for (int i = 0; i < n_in; i++) {
        if (in_sizes[i] == NPTS * INROW) {
            inpt = (const float*)d_in[i];
        } else if (in_sizes[i] == KCENT * DIMK) {
            centers_seen++;
            if (centers_seen == 2) centers1 = (const float*)d_in[i];
        }
    }
    if (!inpt)     inpt     = (const float*)d_in[0];
    if (!centers1) centers1 = (const float*)d_in[n_in - 1];

    float* out = (float*)d_out;

    // Host-side attribute set (idempotent; not a stream op -> capture-legal)
    cudaFuncSetAttribute(label_kernel,
                         cudaFuncAttributeMaxDynamicSharedMemorySize,
                         SMEM_BYTES);

    cnorm_kernel<<<(KCENT + 255) / 256, 256>>>(centers1);
    label_kernel<<<NPTS / BM, THREADS, SMEM_BYTES>>>(inpt, centers1, out);
}

// round 9
// speedup vs baseline: 2.1859x; 2.1859x over previous
#include <cuda_runtime.h>
#include <cstdint>

// Problem constants
#define NPTS   131072
#define DIMK   64
#define KCENT  1024
#define INROW  128

#define THREADS 256          // 8 warps; each warp owns 16 points
#define BM      128          // points per CTA
#define NTILES  (KCENT / 8)  // 128 n8-tiles
#define TPC     8            // tiles per chunk (64 centers)
#define NCHUNK  (NTILES / TPC)           // 16
#define CHUNK_BYTES (TPC * 2 * 8 * 32 * 8)  // 32768
#define CN_OFF  (2 * CHUNK_BYTES)        // after the two chunk buffers
#define SMEM_REQ (CN_OFF + KCENT * 4)    // 69632

__device__ float g_cnorm[KCENT];
// B fragments, tile-major: [tile(128)][split(2)][kstep(8)][lane(32)] x uint2
// uint2 = (b0, b1) = tf32 bits of centers[n][k], centers[n][k+4],
// n = tile*8 + lane/4, k = kstep*8 + lane%4.
__device__ __align__(16) uint2 g_bfrag[NTILES * 2 * 8 * 32];

// ---------------- helpers ----------------
__device__ __forceinline__ unsigned to_tf32(float x) {
    unsigned u;
    asm("cvt.rna.tf32.f32 %0, %1;" : "=r"(u) : "f"(x));
    return u;
}
__device__ __forceinline__ void split_tf32(float x, unsigned& hi, unsigned& lo) {
    hi = to_tf32(x);
    lo = to_tf32(x - __uint_as_float(hi));
}
__device__ __forceinline__ void mma_tf32(float d[4], const unsigned a[4],
                                         unsigned b0, unsigned b1) {
    asm("mma.sync.aligned.m16n8k8.row.col.f32.tf32.tf32.f32 "
        "{%0,%1,%2,%3}, {%4,%5,%6,%7}, {%8,%9}, {%0,%1,%2,%3};"
        : "+f"(d[0]), "+f"(d[1]), "+f"(d[2]), "+f"(d[3])
        : "r"(a[0]), "r"(a[1]), "r"(a[2]), "r"(a[3]), "r"(b0), "r"(b1));
}
__device__ __forceinline__ void cp_async16(unsigned smem_addr, const void* g) {
    asm volatile("cp.async.cg.shared.global [%0], [%1], 16;"
                 :: "r"(smem_addr), "l"(g));
}

// ---------------- prep kernels ----------------
__global__ void cnorm_kernel(const float* __restrict__ centers) {
    int n = blockIdx.x * blockDim.x + threadIdx.x;
    if (n < KCENT) {
        const float* c = centers + (size_t)n * DIMK;
        float s = 0.f;
        #pragma unroll
        for (int k = 0; k < DIMK; k++) s = fmaf(c[k], c[k], s);
        g_cnorm[n] = s;
    }
}

// Build fragment-ordered tf32 hi/lo blob from centers.
__global__ void csplit_kernel(const float* __restrict__ centers) {
    int id = blockIdx.x * blockDim.x + threadIdx.x;   // 128*8*32 = 32768
    if (id >= NTILES * 8 * 32) return;
    int lane = id & 31;
    int q    = (id >> 5) & 7;
    int t    = id >> 8;
    int n = t * 8 + (lane >> 2);
    int k = q * 8 + (lane & 3);
    float x0 = centers[(size_t)n * DIMK + k];
    float x1 = centers[(size_t)n * DIMK + k + 4];
    unsigned h0, l0, h1, l1;
    split_tf32(x0, h0, l0);
    split_tf32(x1, h1, l1);
    g_bfrag[((t * 2 + 0) * 8 + q) * 32 + lane] = make_uint2(h0, h1);
    g_bfrag[((t * 2 + 1) * 8 + q) * 32 + lane] = make_uint2(l0, l1);
}

// ---------------- main: 3xTF32 mma.sync GEMM + fused argmin ----------------
__global__ void __launch_bounds__(THREADS, 2)
label_mma_kernel(const float* __restrict__ inpt, float* __restrict__ out) {
    extern __shared__ __align__(16) unsigned char sm[];
    const unsigned sbase = (unsigned)__cvta_generic_to_shared(sm);
    float* cn_s = reinterpret_cast<float*>(sm + CN_OFF);

    const int tid  = threadIdx.x;
    const int wid  = tid >> 5;
    const int lane = tid & 31;
    const int r    = lane >> 2;   // 0..7
    const int cc   = lane & 3;    // 0..3
    const int m0   = blockIdx.x * BM;
    const int mrow = m0 + wid * 16;

    // Prefetch chunk 0 (linear copy: blob layout == smem layout)
    {
        const unsigned char* src = (const unsigned char*)g_bfrag;
        #pragma unroll
        for (int j = 0; j < CHUNK_BYTES / (THREADS * 16); j++)
            cp_async16(sbase + tid * 16 + j * (THREADS * 16),
                       src + tid * 16 + j * (THREADS * 16));
        asm volatile("cp.async.commit_group;");
    }

    // Center norms -> smem
    for (int i = tid; i < KCENT; i += THREADS) cn_s[i] = g_cnorm[i];

    // A fragments (registers): 8 ksteps x 4 regs, hi+lo
    unsigned ahi[8][4], alo[8][4];
    {
        const float* row0 = inpt + (size_t)(mrow + r) * INROW + DIMK;
        const float* row8 = inpt + (size_t)(mrow + r + 8) * INROW + DIMK;
        #pragma unroll
        for (int q = 0; q < 8; q++) {
            split_tf32(__ldg(row0 + q * 8 + cc),     ahi[q][0], alo[q][0]);
            split_tf32(__ldg(row8 + q * 8 + cc),     ahi[q][1], alo[q][1]);
            split_tf32(__ldg(row0 + q * 8 + cc + 4), ahi[q][2], alo[q][2]);
            split_tf32(__ldg(row8 + q * 8 + cc + 4), ahi[q][3], alo[q][3]);
        }
    }

    // Running first-min per thread: row r (bd0) and row r+8 (bd1)
    float bd0 = __int_as_float(0x7f800000), bd1 = bd0;
    int   bn0 = 0, bn1 = 0;

    #pragma unroll 1
    for (int c = 0; c < NCHUNK; c++) {
        asm volatile("cp.async.wait_group 0;" ::: "memory");
        __syncthreads();   // chunk c visible; all warps done with chunk c-1

        if (c + 1 < NCHUNK) {
            const unsigned char* src =
                (const unsigned char*)g_bfrag + (size_t)(c + 1) * CHUNK_BYTES;
            unsigned dst = sbase + ((c + 1) & 1) * CHUNK_BYTES;
            #pragma unroll
            for (int j = 0; j < CHUNK_BYTES / (THREADS * 16); j++)
                cp_async16(dst + tid * 16 + j * (THREADS * 16),
                           src + tid * 16 + j * (THREADS * 16));
            asm volatile("cp.async.commit_group;");
        }

        const unsigned buf = sbase + (c & 1) * CHUNK_BYTES + lane * 8;

        #pragma unroll
        for (int t8 = 0; t8 < TPC; t8++) {
            float d[4] = {0.f, 0.f, 0.f, 0.f};
            #pragma unroll
            for (int q = 0; q < 8; q++) {
                uint2 bh, bl;
                asm volatile("ld.shared.v2.b32 {%0,%1}, [%2];"
                             : "=r"(bh.x), "=r"(bh.y)
                             : "r"(buf + (((t8 * 2 + 0) * 8 + q) * 32) * 8));
                asm volatile("ld.shared.v2.b32 {%0,%1}, [%2];"
                             : "=r"(bl.x), "=r"(bl.y)
                             : "r"(buf + (((t8 * 2 + 1) * 8 + q) * 32) * 8));
                mma_tf32(d, ahi[q], bh.x, bh.y);   // hi*hi
                mma_tf32(d, ahi[q], bl.x, bl.y);   // hi*lo
                mma_tf32(d, alo[q], bh.x, bh.y);   // lo*hi
            }
            // epilogue: cols n = base + 2cc, base + 2cc + 1
            const int nbase = c * 64 + t8 * 8 + 2 * cc;
            float2 cn = *reinterpret_cast<const float2*>(cn_s + nbase);
            float e0 = fmaf(-2.f, d[0], cn.x);   // row r,   col nbase
            float e1 = fmaf(-2.f, d[1], cn.y);   // row r,   col nbase+1
            float e2 = fmaf(-2.f, d[2], cn.x);   // row r+8, col nbase
            float e3 = fmaf(-2.f, d[3], cn.y);   // row r+8, col nbase+1
            // ascending col order + strict < keeps first-min semantics
            if (e0 < bd0) { bd0 = e0; bn0 = nbase; }
            if (e1 < bd0) { bd0 = e1; bn0 = nbase + 1; }
            if (e2 < bd1) { bd1 = e2; bn1 = nbase; }
            if (e3 < bd1) { bd1 = e3; bn1 = nbase + 1; }
        }
    }

    // Reduce across the 4 lanes sharing each row (disjoint n-sets; tie->lower n)
    #pragma unroll
    for (int off = 1; off <= 2; off <<= 1) {
        float od0 = __shfl_xor_sync(0xffffffffu, bd0, off);
        int   on0 = __shfl_xor_sync(0xffffffffu, bn0, off);
        float od1 = __shfl_xor_sync(0xffffffffu, bd1, off);
        int   on1 = __shfl_xor_sync(0xffffffffu, bn1, off);
        if (od0 < bd0 || (od0 == bd0 && on0 < bn0)) { bd0 = od0; bn0 = on0; }
        if (od1 < bd1 || (od1 == bd1 && on1 < bn1)) { bd1 = od1; bn1 = on1; }
    }
    if (cc == 0) {
        out[mrow + r]     = (float)bn0;   // fp32 output dtype
        out[mrow + r + 8] = (float)bn1;
    }
}

extern "C" void kernel_launch(void* const* d_in, const int* in_sizes, int n_in,
                              void* d_out, int out_size) {
    // Identify inputs by element count:
    //   inpt: 16777216 elements (unique); centers1: second 65536-elem tensor
    const float* inpt     = nullptr;
    const float* centers1 = nullptr;
    int centers_seen = 0;
    for (int i = 0; i < n_in; i++) {
        if (in_sizes[i] == NPTS * INROW) {
            inpt = (const float*)d_in[i];
        } else if (in_sizes[i] == KCENT * DIMK) {
            centers_seen++;
            if (centers_seen == 2) centers1 = (const float*)d_in[i];
        }
    }
    if (!inpt)     inpt     = (const float*)d_in[0];
    if (!centers1) centers1 = (const float*)d_in[n_in - 1];

    float* out = (float*)d_out;

    cudaFuncSetAttribute(label_mma_kernel,
                         cudaFuncAttributeMaxDynamicSharedMemorySize, SMEM_REQ);

    cnorm_kernel<<<(KCENT + 255) / 256, 256>>>(centers1);
    csplit_kernel<<<(NTILES * 8 * 32 + 255) / 256, 256>>>(centers1);
    label_mma_kernel<<<NPTS / BM, THREADS, SMEM_REQ>>>(inpt, out);
}